// round 4
// baseline (speedup 1.0000x reference)
#include <cuda_runtime.h>
#include <cstdint>
#include <math.h>

// Problem constants
#define BB 4
#define LL 2048
#define EE 1024
#define HH 16
#define DD 64
#define ML (BB * LL)   // 8192 total rows

// Scratch (device globals: allocation-free per harness rules)
__device__ float g_q[ML * EE];
__device__ float g_k[ML * EE];
__device__ float g_v[ML * EE];
__device__ float g_ctx[ML * EE];

// ---------------------------------------------------------------------------
// Helpers
// ---------------------------------------------------------------------------
__device__ __forceinline__ uint32_t smem_u32(const void* p) {
    uint32_t a;
    asm("{ .reg .u64 t; cvta.to.shared.u64 t, %1; cvt.u32.u64 %0, t; }"
        : "=r"(a) : "l"(p));
    return a;
}

#define CP_ASYNC16(smem_addr, gptr) \
    asm volatile("cp.async.cg.shared.global [%0], [%1], 16;" \
                 :: "r"(smem_addr), "l"(gptr) : "memory")

__device__ __forceinline__ uint32_t f2tf(float f) {
    uint32_t r;
    asm("cvt.rna.tf32.f32 %0, %1;" : "=r"(r) : "f"(f));
    return r;
}

__device__ __forceinline__ void mma_tf32(float* c, const uint32_t* a,
                                         const uint32_t* b) {
    asm volatile(
        "mma.sync.aligned.m16n8k8.row.col.f32.tf32.tf32.f32 "
        "{%0,%1,%2,%3}, {%4,%5,%6,%7}, {%8,%9}, {%0,%1,%2,%3};"
        : "+f"(c[0]), "+f"(c[1]), "+f"(c[2]), "+f"(c[3])
        : "r"(a[0]), "r"(a[1]), "r"(a[2]), "r"(a[3]), "r"(b[0]), "r"(b[1]));
}

// ---------------------------------------------------------------------------
// mma.sync tf32 GEMM: C[M,N] = A[M,K] @ W[N,K]^T (+bias). M=8192, N=K=1024.
// CTA tile 128x128, BK=32, 256 threads (8 warps, 2x4 grid, 64x32 warp tile).
// Double-buffered cp.async. Both operands K-major => mma row.col directly.
// ---------------------------------------------------------------------------
#define GBK 32
#define NKT32 (EE / GBK)        // 32 k-tiles
#define SSTR 40                 // smem row stride in floats (160B, 16B-aligned)
#define TILE_F (128 * SSTR)     // floats per matrix tile
#define STAGE_F (2 * TILE_F)    // A + W per stage
#define GEMM_SMEM (2 * STAGE_F * 4)   // 2 stages = 81920 bytes

__global__ __launch_bounds__(256, 2) void gemm_mma(const float* __restrict__ A,
                                                   const float* __restrict__ W,
                                                   const float* __restrict__ bias,
                                                   float* __restrict__ C) {
    extern __shared__ float sm[];
    const int tid = threadIdx.x;
    const int lane = tid & 31;
    const int warp = tid >> 5;
    const int wm = (warp >> 2) * 64;   // warp m-offset within CTA tile
    const int wn = (warp & 3) * 32;    // warp n-offset
    const int bm = blockIdx.x * 128;
    const int bn = blockIdx.y * 128;
    const uint32_t sb = smem_u32(sm);

    // load geometry: each thread does 4 float4 for A and 4 for W per stage
    const int lrow = tid >> 3;          // 0..31
    const int lc4 = (tid & 7) * 4;      // float col in [0,32)

    const int lg = lane >> 2;           // 0..7 (fragment row group)
    const int lk = lane & 3;            // 0..3 (fragment k within half)

    float c[4][4][4];
#pragma unroll
    for (int mt = 0; mt < 4; mt++)
#pragma unroll
        for (int nt = 0; nt < 4; nt++)
#pragma unroll
            for (int i = 0; i < 4; i++) c[mt][nt][i] = 0.0f;

    const float* gA0 = A + (size_t)(bm + lrow) * EE + lc4;
    const float* gW0 = W + (size_t)(bn + lrow) * EE + lc4;
    const uint32_t sOff = (lrow * SSTR + lc4) * 4;

#define LOAD_STAGE(kt, s) do {                                                 \
        const float* _ga = gA0 + (size_t)(kt) * GBK;                           \
        const float* _gw = gW0 + (size_t)(kt) * GBK;                           \
        uint32_t _sa = sb + (uint32_t)((s) * STAGE_F * 4) + sOff;              \
        uint32_t _sw = _sa + TILE_F * 4;                                       \
        _Pragma("unroll")                                                      \
        for (int _u = 0; _u < 4; _u++) {                                       \
            CP_ASYNC16(_sa + _u * 32 * SSTR * 4, _ga + (size_t)_u * 32 * EE);  \
            CP_ASYNC16(_sw + _u * 32 * SSTR * 4, _gw + (size_t)_u * 32 * EE);  \
        }                                                                      \
        asm volatile("cp.async.commit_group;" ::: "memory");                   \
    } while (0)

    LOAD_STAGE(0, 0);

    for (int kt = 0; kt < NKT32; kt++) {
        const int buf = kt & 1;
        if (kt + 1 < NKT32) {
            LOAD_STAGE(kt + 1, buf ^ 1);
            asm volatile("cp.async.wait_group 1;" ::: "memory");
        } else {
            asm volatile("cp.async.wait_group 0;" ::: "memory");
        }
        __syncthreads();

        const float* As = sm + buf * STAGE_F;
        const float* Ws = As + TILE_F;

#pragma unroll
        for (int ks = 0; ks < 4; ks++) {
            const int k0 = ks * 8;
            uint32_t bfr[4][2];
            uint32_t afr[4][4];
#pragma unroll
            for (int nt = 0; nt < 4; nt++) {
                const int r = wn + nt * 8 + lg;
                bfr[nt][0] = f2tf(Ws[r * SSTR + k0 + lk]);
                bfr[nt][1] = f2tf(Ws[r * SSTR + k0 + 4 + lk]);
            }
#pragma unroll
            for (int mt = 0; mt < 4; mt++) {
                const int r = wm + mt * 16 + lg;
                afr[mt][0] = f2tf(As[r * SSTR + k0 + lk]);
                afr[mt][1] = f2tf(As[(r + 8) * SSTR + k0 + lk]);
                afr[mt][2] = f2tf(As[r * SSTR + k0 + 4 + lk]);
                afr[mt][3] = f2tf(As[(r + 8) * SSTR + k0 + 4 + lk]);
            }
#pragma unroll
            for (int mt = 0; mt < 4; mt++)
#pragma unroll
                for (int nt = 0; nt < 4; nt++)
                    mma_tf32(c[mt][nt], afr[mt], bfr[nt]);
        }
        __syncthreads();
    }

    // Epilogue: direct float2 stores (+bias)
#pragma unroll
    for (int mt = 0; mt < 4; mt++) {
        const int r0 = bm + wm + mt * 16 + lg;
#pragma unroll
        for (int nt = 0; nt < 4; nt++) {
            const int col = bn + wn + nt * 8 + lk * 2;
            float bx = 0.0f, by = 0.0f;
            if (bias) { bx = bias[col]; by = bias[col + 1]; }
            float2 v0, v1;
            v0.x = c[mt][nt][0] + bx;
            v0.y = c[mt][nt][1] + by;
            v1.x = c[mt][nt][2] + bx;
            v1.y = c[mt][nt][3] + by;
            *(float2*)(C + (size_t)r0 * EE + col) = v0;
            *(float2*)(C + (size_t)(r0 + 8) * EE + col) = v1;
        }
    }
}

// ---------------------------------------------------------------------------
// Fused attention (flash-style, fp32) — unchanged (known-good).
// ---------------------------------------------------------------------------
#define BR 64
#define BC 64
#define KSTR 65

#define ATTN_SMEM_BYTES ((BR * 64 + 3 * BC * KSTR) * 4)

__global__ __launch_bounds__(256) void attn_kernel(const int* __restrict__ mask) {
    extern __shared__ float sm[];
    float* Qs = sm;
    float* Ks = Qs + BR * 64;
    float* Vs = Ks + BC * KSTR;
    float* Ps = Vs + BC * KSTR;

    const int tid = threadIdx.x;
    const int bh = blockIdx.y;
    const int b = bh >> 4;
    const int h = bh & 15;
    const int q0 = blockIdx.x * BR;
    const int tx = tid & 15;
    const int ty = tid >> 4;
    const int r0 = ty * 4;
    const int c0 = tx * 4;

    const float scale = 0.03125f;
    const float mask_addend = -3.125e18f;

#pragma unroll
    for (int t = 0; t < 4; t++) {
        int f4 = tid + 256 * t;
        int row = f4 >> 4;
        int col = (f4 & 15) << 2;
        float4 q = *(const float4*)(g_q + (size_t)(b * LL + q0 + row) * EE + h * DD + col);
        Qs[row * 64 + col + 0] = q.x * scale;
        Qs[row * 64 + col + 1] = q.y * scale;
        Qs[row * 64 + col + 2] = q.z * scale;
        Qs[row * 64 + col + 3] = q.w * scale;
    }

    float o[4][4];
    float mrow[4], lrow[4];
#pragma unroll
    for (int i = 0; i < 4; i++) {
        mrow[i] = -1e30f;
        lrow[i] = 0.0f;
#pragma unroll
        for (int j = 0; j < 4; j++) o[i][j] = 0.0f;
    }

    const size_t mask_b = (size_t)b * LL * LL;

    for (int kt = 0; kt < LL / BC; kt++) {
        const int k0 = kt * BC;
        __syncthreads();

#pragma unroll
        for (int t = 0; t < 4; t++) {
            int f4 = tid + 256 * t;
            int row = f4 >> 4;
            int col = (f4 & 15) << 2;
            size_t g = (size_t)(b * LL + k0 + row) * EE + h * DD + col;
            float4 kv = *(const float4*)(g_k + g);
            Ks[row * KSTR + col + 0] = kv.x;
            Ks[row * KSTR + col + 1] = kv.y;
            Ks[row * KSTR + col + 2] = kv.z;
            Ks[row * KSTR + col + 3] = kv.w;
            float4 vv = *(const float4*)(g_v + g);
            Vs[row * KSTR + col + 0] = vv.x;
            Vs[row * KSTR + col + 1] = vv.y;
            Vs[row * KSTR + col + 2] = vv.z;
            Vs[row * KSTR + col + 3] = vv.w;
            int4 mm = *(const int4*)(mask + mask_b + (size_t)(q0 + row) * LL + k0 + col);
            Ps[row * KSTR + col + 0] = (mm.x != 0) ? 0.0f : mask_addend;
            Ps[row * KSTR + col + 1] = (mm.y != 0) ? 0.0f : mask_addend;
            Ps[row * KSTR + col + 2] = (mm.z != 0) ? 0.0f : mask_addend;
            Ps[row * KSTR + col + 3] = (mm.w != 0) ? 0.0f : mask_addend;
        }
        __syncthreads();

        float s[4][4];
#pragma unroll
        for (int i = 0; i < 4; i++)
#pragma unroll
            for (int j = 0; j < 4; j++)
                s[i][j] = Ps[(r0 + i) * KSTR + (c0 + j)];

#pragma unroll 16
        for (int d = 0; d < DD; d++) {
            float qv[4], kv[4];
#pragma unroll
            for (int i = 0; i < 4; i++) qv[i] = Qs[(r0 + i) * 64 + d];
#pragma unroll
            for (int j = 0; j < 4; j++) kv[j] = Ks[(c0 + j) * KSTR + d];
#pragma unroll
            for (int i = 0; i < 4; i++)
#pragma unroll
                for (int j = 0; j < 4; j++) s[i][j] += qv[i] * kv[j];
        }

#pragma unroll
        for (int i = 0; i < 4; i++) {
            float mx = s[i][0];
#pragma unroll
            for (int j = 1; j < 4; j++) mx = fmaxf(mx, s[i][j]);
#pragma unroll
            for (int w = 8; w > 0; w >>= 1)
                mx = fmaxf(mx, __shfl_xor_sync(0xffffffffu, mx, w));
            float mnew = fmaxf(mrow[i], mx);
            float alpha = __expf(mrow[i] - mnew);
            mrow[i] = mnew;
            float psum = 0.0f;
#pragma unroll
            for (int j = 0; j < 4; j++) {
                s[i][j] = __expf(s[i][j] - mnew);
                psum += s[i][j];
            }
#pragma unroll
            for (int w = 8; w > 0; w >>= 1)
                psum += __shfl_xor_sync(0xffffffffu, psum, w);
            lrow[i] = lrow[i] * alpha + psum;
#pragma unroll
            for (int j = 0; j < 4; j++) {
                o[i][j] *= alpha;
                Ps[(r0 + i) * KSTR + (c0 + j)] = s[i][j];
            }
        }
        __syncthreads();

#pragma unroll 8
        for (int c = 0; c < BC; c++) {
            float pv[4], vv[4];
#pragma unroll
            for (int i = 0; i < 4; i++) pv[i] = Ps[(r0 + i) * KSTR + c];
#pragma unroll
            for (int j = 0; j < 4; j++) vv[j] = Vs[c * KSTR + (c0 + j)];
#pragma unroll
            for (int i = 0; i < 4; i++)
#pragma unroll
                for (int j = 0; j < 4; j++) o[i][j] += pv[i] * vv[j];
        }
    }

#pragma unroll
    for (int i = 0; i < 4; i++) {
        float inv = 1.0f / lrow[i];
        size_t base = (size_t)(b * LL + q0 + r0 + i) * EE + h * DD + c0;
        float4 v;
        v.x = o[i][0] * inv;
        v.y = o[i][1] * inv;
        v.z = o[i][2] * inv;
        v.w = o[i][3] * inv;
        *(float4*)(g_ctx + base) = v;
    }
}

// ---------------------------------------------------------------------------
// Launch
// ---------------------------------------------------------------------------
extern "C" void kernel_launch(void* const* d_in, const int* in_sizes, int n_in,
                              void* d_out, int out_size) {
    const float* queries = (const float*)d_in[0];
    const float* keys    = (const float*)d_in[1];
    const float* values  = (const float*)d_in[2];
    const int*   mask    = (const int*)d_in[3];
    const float* Wq      = (const float*)d_in[4];
    const float* Wk      = (const float*)d_in[5];
    const float* Wv      = (const float*)d_in[6];
    const float* Wo      = (const float*)d_in[7];
    const float* bo      = (const float*)d_in[8];
    float* out = (float*)d_out;

    float *q, *k, *v, *ctx;
    cudaGetSymbolAddress((void**)&q,   g_q);
    cudaGetSymbolAddress((void**)&k,   g_k);
    cudaGetSymbolAddress((void**)&v,   g_v);
    cudaGetSymbolAddress((void**)&ctx, g_ctx);

    cudaFuncSetAttribute(gemm_mma, cudaFuncAttributeMaxDynamicSharedMemorySize,
                         GEMM_SMEM);
    cudaFuncSetAttribute(attn_kernel, cudaFuncAttributeMaxDynamicSharedMemorySize,
                         ATTN_SMEM_BYTES);

    dim3 gg(ML / 128, EE / 128);   // 64 x 8
    gemm_mma<<<gg, 256, GEMM_SMEM>>>(queries, Wq, nullptr, q);
    gemm_mma<<<gg, 256, GEMM_SMEM>>>(keys,    Wk, nullptr, k);
    gemm_mma<<<gg, 256, GEMM_SMEM>>>(values,  Wv, nullptr, v);

    dim3 ga(LL / BR, BB * HH);     // 32 x 64
    attn_kernel<<<ga, 256, ATTN_SMEM_BYTES>>>(mask);

    gemm_mma<<<gg, 256, GEMM_SMEM>>>(ctx, Wo, bo, out);
}

// round 5
// speedup vs baseline: 2.3450x; 2.3450x over previous
#include <cuda_runtime.h>
#include <cstdint>
#include <math.h>

// Problem constants
#define BB 4
#define LL 2048
#define EE 1024
#define HH 16
#define DD 64
#define ML (BB * LL)   // 8192 total rows

// Scratch (device globals: allocation-free per harness rules)
__device__ float g_q[ML * EE];
__device__ float g_k[ML * EE];
__device__ float g_v[ML * EE];
__device__ float g_ctx[ML * EE];
__device__ float g_rq[ML * EE];
__device__ float g_rk[ML * EE];
__device__ float g_rv[ML * EE];
__device__ float g_rw[4 * EE * EE];

// ---------------------------------------------------------------------------
// Helpers
// ---------------------------------------------------------------------------
__device__ __forceinline__ uint32_t smem_u32(const void* p) {
    uint32_t a;
    asm("{ .reg .u64 t; cvta.to.shared.u64 t, %1; cvt.u32.u64 %0, t; }"
        : "=r"(a) : "l"(p));
    return a;
}

#define CP_ASYNC16(smem_addr, gptr) \
    asm volatile("cp.async.cg.shared.global [%0], [%1], 16;" \
                 :: "r"(smem_addr), "l"(gptr) : "memory")

__device__ __forceinline__ float rna(float f) {
    uint32_t r;
    asm("cvt.rna.tf32.f32 %0, %1;" : "=r"(r) : "f"(f));
    return __uint_as_float(r);
}

__device__ __forceinline__ void mma_tf32(float* c, const uint32_t* a,
                                         const uint32_t* b) {
    asm volatile(
        "mma.sync.aligned.m16n8k8.row.col.f32.tf32.tf32.f32 "
        "{%0,%1,%2,%3}, {%4,%5,%6,%7}, {%8,%9}, {%0,%1,%2,%3};"
        : "+f"(c[0]), "+f"(c[1]), "+f"(c[2]), "+f"(c[3])
        : "r"(a[0]), "r"(a[1]), "r"(a[2]), "r"(a[3]), "r"(b[0]), "r"(b[1]));
}

// ---------------------------------------------------------------------------
// Pre-rounding pass: out[i] = tf32_rna(in[i]) (one-time, memory-bound)
// ---------------------------------------------------------------------------
__global__ void round_tf32(const float* __restrict__ in, float* __restrict__ out,
                           int n4) {
    int i = blockIdx.x * blockDim.x + threadIdx.x;
    int stride = gridDim.x * blockDim.x;
    for (; i < n4; i += stride) {
        float4 v = ((const float4*)in)[i];
        v.x = rna(v.x); v.y = rna(v.y); v.z = rna(v.z); v.w = rna(v.w);
        ((float4*)out)[i] = v;
    }
}

// ---------------------------------------------------------------------------
// mma.sync tf32 GEMM: C[M,N] = A[M,K] @ W[N,K]^T (+bias). Inputs pre-rounded
// to tf32 (no cvt in inner loop). CTA 128x128, BK=32, 8 warps (2x4, 64x32).
// SSTR=36 -> conflict-free fragment loads ((4*lg+lk)=lane covers all banks).
// ROUND_OUT: round outputs to tf32 in epilogue (for attention consumption).
// ---------------------------------------------------------------------------
#define GBK 32
#define NKT32 (EE / GBK)
#define SSTR 36
#define TILE_F (128 * SSTR)
#define STAGE_F (2 * TILE_F)
#define GEMM_SMEM (2 * STAGE_F * 4)   // 73728 B

template <int ROUND_OUT>
__global__ __launch_bounds__(256, 2) void gemm_mma(const float* __restrict__ A,
                                                   const float* __restrict__ W,
                                                   const float* __restrict__ bias,
                                                   float* __restrict__ C) {
    extern __shared__ float sm[];
    const int tid = threadIdx.x;
    const int lane = tid & 31;
    const int warp = tid >> 5;
    const int wm = (warp >> 2) * 64;
    const int wn = (warp & 3) * 32;
    const int bm = blockIdx.x * 128;
    const int bn = blockIdx.y * 128;
    const uint32_t sb = smem_u32(sm);

    const int lrow = tid >> 3;
    const int lc4 = (tid & 7) * 4;
    const int lg = lane >> 2;
    const int lk = lane & 3;

    float c[4][4][4];
#pragma unroll
    for (int mt = 0; mt < 4; mt++)
#pragma unroll
        for (int nt = 0; nt < 4; nt++)
#pragma unroll
            for (int i = 0; i < 4; i++) c[mt][nt][i] = 0.0f;

    const float* gA0 = A + (size_t)(bm + lrow) * EE + lc4;
    const float* gW0 = W + (size_t)(bn + lrow) * EE + lc4;
    const uint32_t sOff = (lrow * SSTR + lc4) * 4;

#define LOAD_STAGE(kt, s) do {                                                 \
        const float* _ga = gA0 + (size_t)(kt) * GBK;                           \
        const float* _gw = gW0 + (size_t)(kt) * GBK;                           \
        uint32_t _sa = sb + (uint32_t)((s) * STAGE_F * 4) + sOff;              \
        uint32_t _sw = _sa + TILE_F * 4;                                       \
        _Pragma("unroll")                                                      \
        for (int _u = 0; _u < 4; _u++) {                                       \
            CP_ASYNC16(_sa + _u * 32 * SSTR * 4, _ga + (size_t)_u * 32 * EE);  \
            CP_ASYNC16(_sw + _u * 32 * SSTR * 4, _gw + (size_t)_u * 32 * EE);  \
        }                                                                      \
        asm volatile("cp.async.commit_group;" ::: "memory");                   \
    } while (0)

    LOAD_STAGE(0, 0);

    for (int kt = 0; kt < NKT32; kt++) {
        const int buf = kt & 1;
        if (kt + 1 < NKT32) {
            LOAD_STAGE(kt + 1, buf ^ 1);
            asm volatile("cp.async.wait_group 1;" ::: "memory");
        } else {
            asm volatile("cp.async.wait_group 0;" ::: "memory");
        }
        __syncthreads();

        const float* As = sm + buf * STAGE_F;
        const float* Ws = As + TILE_F;

#pragma unroll
        for (int ks = 0; ks < 4; ks++) {
            const int k0 = ks * 8;
            uint32_t bfr[4][2];
            uint32_t afr[4][4];
#pragma unroll
            for (int nt = 0; nt < 4; nt++) {
                const int r = wn + nt * 8 + lg;
                bfr[nt][0] = __float_as_uint(Ws[r * SSTR + k0 + lk]);
                bfr[nt][1] = __float_as_uint(Ws[r * SSTR + k0 + 4 + lk]);
            }
#pragma unroll
            for (int mt = 0; mt < 4; mt++) {
                const int r = wm + mt * 16 + lg;
                afr[mt][0] = __float_as_uint(As[r * SSTR + k0 + lk]);
                afr[mt][1] = __float_as_uint(As[(r + 8) * SSTR + k0 + lk]);
                afr[mt][2] = __float_as_uint(As[r * SSTR + k0 + 4 + lk]);
                afr[mt][3] = __float_as_uint(As[(r + 8) * SSTR + k0 + 4 + lk]);
            }
#pragma unroll
            for (int mt = 0; mt < 4; mt++)
#pragma unroll
                for (int nt = 0; nt < 4; nt++)
                    mma_tf32(c[mt][nt], afr[mt], bfr[nt]);
        }
        __syncthreads();
    }

#pragma unroll
    for (int mt = 0; mt < 4; mt++) {
        const int r0 = bm + wm + mt * 16 + lg;
#pragma unroll
        for (int nt = 0; nt < 4; nt++) {
            const int col = bn + wn + nt * 8 + lk * 2;
            float bx = 0.0f, by = 0.0f;
            if (bias) { bx = bias[col]; by = bias[col + 1]; }
            float2 v0, v1;
            v0.x = c[mt][nt][0] + bx;
            v0.y = c[mt][nt][1] + by;
            v1.x = c[mt][nt][2] + bx;
            v1.y = c[mt][nt][3] + by;
            if (ROUND_OUT) {
                v0.x = rna(v0.x); v0.y = rna(v0.y);
                v1.x = rna(v1.x); v1.y = rna(v1.y);
            }
            *(float2*)(C + (size_t)r0 * EE + col) = v0;
            *(float2*)(C + (size_t)(r0 + 8) * EE + col) = v1;
        }
    }
}

// ---------------------------------------------------------------------------
// Tensor-core flash attention (tf32 mma, fp32 softmax).
// CTA: 128 q-rows x one (b,h). 8 warps, warp = 16 q-rows x full 64-col tile.
// K-tiles of 64 keys, online softmax on c-fragments.
// Inputs g_q/g_k/g_v are tf32-pre-rounded by GEMM epilogues.
// Strides: AQ/AK/AP = 68 ((4*lg+lk)=lane, conflict-free), AV = 72 ((8*lk+lg)).
// ---------------------------------------------------------------------------
#define AQ 68
#define AK 68
#define AV 72
#define AP 68
#define ATTN_SMEM ((128 * AQ + 64 * AK + 64 * AV + 128 * AP) * 4)  // 105472 B

__global__ __launch_bounds__(256, 2) void attn_tc(const int* __restrict__ mask) {
    extern __shared__ float sm[];
    float* Qs = sm;                    // [128][68]
    float* Ks = Qs + 128 * AQ;         // [64][68]
    float* Vs = Ks + 64 * AK;          // [64][72]
    float* Ps = Vs + 64 * AV;          // [128][68]  mask addend, then P

    const int tid = threadIdx.x;
    const int lane = tid & 31;
    const int warp = tid >> 5;
    const int lg = lane >> 2;
    const int lk = lane & 3;
    const int wq = warp * 16;

    const int bh = blockIdx.y;
    const int b = bh >> 4;
    const int h = bh & 15;
    const int q0 = blockIdx.x * 128;

    const float scale = 0.03125f;          // 1/sqrt(1024) = 2^-5 (exact in tf32)
    const float mask_addend = -3.125e18f;  // -1e20 * scale

    // Load Q tile (pre-scaled; scale is a power of 2 so values stay tf32-exact)
#pragma unroll
    for (int u = 0; u < 8; u++) {
        int idx = tid + 256 * u;
        int row = idx >> 4;
        int c = (idx & 15) << 2;
        float4 q = *(const float4*)(g_q + (size_t)(b * LL + q0 + row) * EE + h * DD + c);
        q.x *= scale; q.y *= scale; q.z *= scale; q.w *= scale;
        *(float4*)(Qs + row * AQ + c) = q;
    }

    float o[8][4];
#pragma unroll
    for (int dn = 0; dn < 8; dn++)
#pragma unroll
        for (int j = 0; j < 4; j++) o[dn][j] = 0.0f;
    float m0 = -1e30f, m1 = -1e30f, l0 = 0.0f, l1 = 0.0f;

    const size_t mask_b = (size_t)b * LL * LL;

    for (int kt = 0; kt < LL / 64; kt++) {
        const int k0g = kt * 64;
        __syncthreads();   // protect Ks/Vs/Ps from previous iteration's readers

        // Load K, V (64x64) and mask addend (128x64 into Ps)
#pragma unroll
        for (int u = 0; u < 4; u++) {
            int idx = tid + 256 * u;
            int row = idx >> 4;
            int c = (idx & 15) << 2;
            size_t g = (size_t)(b * LL + k0g + row) * EE + h * DD + c;
            *(float4*)(Ks + row * AK + c) = *(const float4*)(g_k + g);
            *(float4*)(Vs + row * AV + c) = *(const float4*)(g_v + g);
        }
#pragma unroll
        for (int u = 0; u < 8; u++) {
            int idx = tid + 256 * u;
            int row = idx >> 4;
            int c = (idx & 15) << 2;
            int4 mm = *(const int4*)(mask + mask_b + (size_t)(q0 + row) * LL + k0g + c);
            float4 ad;
            ad.x = (mm.x != 0) ? 0.0f : mask_addend;
            ad.y = (mm.y != 0) ? 0.0f : mask_addend;
            ad.z = (mm.z != 0) ? 0.0f : mask_addend;
            ad.w = (mm.w != 0) ? 0.0f : mask_addend;
            *(float4*)(Ps + row * AP + c) = ad;
        }
        __syncthreads();

        // S = Q @ K^T + mask addend  (c-frags: rows wq+lg / wq+lg+8)
        float s[8][4];
#pragma unroll
        for (int nt = 0; nt < 8; nt++) {
            float2 t0 = *(float2*)(Ps + (wq + lg) * AP + nt * 8 + 2 * lk);
            float2 t1 = *(float2*)(Ps + (wq + lg + 8) * AP + nt * 8 + 2 * lk);
            s[nt][0] = t0.x; s[nt][1] = t0.y;
            s[nt][2] = t1.x; s[nt][3] = t1.y;
        }
#pragma unroll
        for (int ks = 0; ks < 8; ks++) {
            const int k0 = ks * 8;
            uint32_t a[4];
            a[0] = __float_as_uint(Qs[(wq + lg) * AQ + k0 + lk]);
            a[1] = __float_as_uint(Qs[(wq + lg + 8) * AQ + k0 + lk]);
            a[2] = __float_as_uint(Qs[(wq + lg) * AQ + k0 + 4 + lk]);
            a[3] = __float_as_uint(Qs[(wq + lg + 8) * AQ + k0 + 4 + lk]);
#pragma unroll
            for (int nt = 0; nt < 8; nt++) {
                uint32_t bf[2];
                bf[0] = __float_as_uint(Ks[(nt * 8 + lg) * AK + k0 + lk]);
                bf[1] = __float_as_uint(Ks[(nt * 8 + lg) * AK + k0 + 4 + lk]);
                mma_tf32(s[nt], a, bf);
            }
        }

        // Online softmax (rows lg and lg+8; each row spans the 4 lanes of a quad)
        float mx0 = s[0][0], mx1 = s[0][2];
#pragma unroll
        for (int nt = 0; nt < 8; nt++) {
            mx0 = fmaxf(mx0, fmaxf(s[nt][0], s[nt][1]));
            mx1 = fmaxf(mx1, fmaxf(s[nt][2], s[nt][3]));
        }
        mx0 = fmaxf(mx0, __shfl_xor_sync(0xffffffffu, mx0, 1));
        mx0 = fmaxf(mx0, __shfl_xor_sync(0xffffffffu, mx0, 2));
        mx1 = fmaxf(mx1, __shfl_xor_sync(0xffffffffu, mx1, 1));
        mx1 = fmaxf(mx1, __shfl_xor_sync(0xffffffffu, mx1, 2));
        float mn0 = fmaxf(m0, mx0), mn1 = fmaxf(m1, mx1);
        float al0 = __expf(m0 - mn0), al1 = __expf(m1 - mn1);
        m0 = mn0; m1 = mn1;
        float sum0 = 0.0f, sum1 = 0.0f;
#pragma unroll
        for (int nt = 0; nt < 8; nt++) {
            s[nt][0] = __expf(s[nt][0] - mn0);
            s[nt][1] = __expf(s[nt][1] - mn0);
            s[nt][2] = __expf(s[nt][2] - mn1);
            s[nt][3] = __expf(s[nt][3] - mn1);
            sum0 += s[nt][0] + s[nt][1];
            sum1 += s[nt][2] + s[nt][3];
        }
        sum0 += __shfl_xor_sync(0xffffffffu, sum0, 1);
        sum0 += __shfl_xor_sync(0xffffffffu, sum0, 2);
        sum1 += __shfl_xor_sync(0xffffffffu, sum1, 1);
        sum1 += __shfl_xor_sync(0xffffffffu, sum1, 2);
        l0 = l0 * al0 + sum0;
        l1 = l1 * al1 + sum1;
#pragma unroll
        for (int dn = 0; dn < 8; dn++) {
            o[dn][0] *= al0; o[dn][1] *= al0;
            o[dn][2] *= al1; o[dn][3] *= al1;
        }

        // Store P (tf32-rounded) into the same cells the addend was read from
#pragma unroll
        for (int nt = 0; nt < 8; nt++) {
            float2 t0, t1;
            t0.x = rna(s[nt][0]); t0.y = rna(s[nt][1]);
            t1.x = rna(s[nt][2]); t1.y = rna(s[nt][3]);
            *(float2*)(Ps + (wq + lg) * AP + nt * 8 + 2 * lk) = t0;
            *(float2*)(Ps + (wq + lg + 8) * AP + nt * 8 + 2 * lk) = t1;
        }
        __syncwarp();   // P rows wq..wq+15 written & read only by this warp

        // O += P @ V
#pragma unroll
        for (int ks = 0; ks < 8; ks++) {
            const int k0 = ks * 8;
            uint32_t a[4];
            a[0] = __float_as_uint(Ps[(wq + lg) * AP + k0 + lk]);
            a[1] = __float_as_uint(Ps[(wq + lg + 8) * AP + k0 + lk]);
            a[2] = __float_as_uint(Ps[(wq + lg) * AP + k0 + 4 + lk]);
            a[3] = __float_as_uint(Ps[(wq + lg + 8) * AP + k0 + 4 + lk]);
#pragma unroll
            for (int dn = 0; dn < 8; dn++) {
                uint32_t bf[2];
                bf[0] = __float_as_uint(Vs[(k0 + lk) * AV + dn * 8 + lg]);
                bf[1] = __float_as_uint(Vs[(k0 + 4 + lk) * AV + dn * 8 + lg]);
                mma_tf32(o[dn], a, bf);
            }
        }
    }

    // Epilogue: normalize, round to tf32 (final GEMM consumes this), store ctx
    float inv0 = 1.0f / l0, inv1 = 1.0f / l1;
    const size_t r0 = (size_t)(b * LL + q0 + wq + lg) * EE + h * DD;
    const size_t r1 = (size_t)(b * LL + q0 + wq + lg + 8) * EE + h * DD;
#pragma unroll
    for (int dn = 0; dn < 8; dn++) {
        const int col = dn * 8 + 2 * lk;
        float2 v0, v1;
        v0.x = rna(o[dn][0] * inv0); v0.y = rna(o[dn][1] * inv0);
        v1.x = rna(o[dn][2] * inv1); v1.y = rna(o[dn][3] * inv1);
        *(float2*)(g_ctx + r0 + col) = v0;
        *(float2*)(g_ctx + r1 + col) = v1;
    }
}

// ---------------------------------------------------------------------------
// Launch
// ---------------------------------------------------------------------------
extern "C" void kernel_launch(void* const* d_in, const int* in_sizes, int n_in,
                              void* d_out, int out_size) {
    const float* queries = (const float*)d_in[0];
    const float* keys    = (const float*)d_in[1];
    const float* values  = (const float*)d_in[2];
    const int*   mask    = (const int*)d_in[3];
    const float* Wq      = (const float*)d_in[4];
    const float* Wk      = (const float*)d_in[5];
    const float* Wv      = (const float*)d_in[6];
    const float* Wo      = (const float*)d_in[7];
    const float* bo      = (const float*)d_in[8];
    float* out = (float*)d_out;

    float *q, *k, *v, *ctx, *rq, *rk, *rv, *rw;
    cudaGetSymbolAddress((void**)&q,   g_q);
    cudaGetSymbolAddress((void**)&k,   g_k);
    cudaGetSymbolAddress((void**)&v,   g_v);
    cudaGetSymbolAddress((void**)&ctx, g_ctx);
    cudaGetSymbolAddress((void**)&rq,  g_rq);
    cudaGetSymbolAddress((void**)&rk,  g_rk);
    cudaGetSymbolAddress((void**)&rv,  g_rv);
    cudaGetSymbolAddress((void**)&rw,  g_rw);

    cudaFuncSetAttribute(gemm_mma<0>, cudaFuncAttributeMaxDynamicSharedMemorySize,
                         GEMM_SMEM);
    cudaFuncSetAttribute(gemm_mma<1>, cudaFuncAttributeMaxDynamicSharedMemorySize,
                         GEMM_SMEM);
    cudaFuncSetAttribute(attn_tc, cudaFuncAttributeMaxDynamicSharedMemorySize,
                         ATTN_SMEM);

    // Pre-round inputs + weights to tf32 (RNA) once
    const int n4in = ML * EE / 4;
    const int n4w  = EE * EE / 4;
    round_tf32<<<512, 256>>>(queries, rq, n4in);
    round_tf32<<<512, 256>>>(keys,    rk, n4in);
    round_tf32<<<512, 256>>>(values,  rv, n4in);
    round_tf32<<<256, 256>>>(Wq, rw + 0 * EE * EE, n4w);
    round_tf32<<<256, 256>>>(Wk, rw + 1 * EE * EE, n4w);
    round_tf32<<<256, 256>>>(Wv, rw + 2 * EE * EE, n4w);
    round_tf32<<<256, 256>>>(Wo, rw + 3 * EE * EE, n4w);

    dim3 gg(ML / 128, EE / 128);   // 64 x 8
    gemm_mma<1><<<gg, 256, GEMM_SMEM>>>(rq, rw + 0 * EE * EE, nullptr, q);
    gemm_mma<1><<<gg, 256, GEMM_SMEM>>>(rk, rw + 1 * EE * EE, nullptr, k);
    gemm_mma<1><<<gg, 256, GEMM_SMEM>>>(rv, rw + 2 * EE * EE, nullptr, v);

    dim3 ga(LL / 128, BB * HH);    // 16 x 64
    attn_tc<<<ga, 256, ATTN_SMEM>>>(mask);

    gemm_mma<0><<<gg, 256, GEMM_SMEM>>>(ctx, rw + 3 * EE * EE, bo, out);
}

// round 7
// speedup vs baseline: 3.6711x; 1.5655x over previous
#include <cuda_runtime.h>
#include <cstdint>
#include <math.h>

// Problem constants
#define BB 4
#define LL 2048
#define EE 1024
#define HH 16
#define DD 64
#define ML (BB * LL)   // 8192 total rows

// Scratch (device globals: allocation-free per harness rules)
__device__ float g_q[ML * EE];
__device__ float g_k[ML * EE];
__device__ float g_v[ML * EE];
__device__ float g_ctx[ML * EE];
__device__ float g_rq[ML * EE];
__device__ float g_rk[ML * EE];
__device__ float g_rv[ML * EE];
__device__ float g_rw[4 * EE * EE];

// ---------------------------------------------------------------------------
// Helpers
// ---------------------------------------------------------------------------
__device__ __forceinline__ uint32_t smem_u32(const void* p) {
    uint32_t a;
    asm("{ .reg .u64 t; cvta.to.shared.u64 t, %1; cvt.u32.u64 %0, t; }"
        : "=r"(a) : "l"(p));
    return a;
}

#define CP_ASYNC16(smem_addr, gptr) \
    asm volatile("cp.async.cg.shared.global [%0], [%1], 16;" \
                 :: "r"(smem_addr), "l"(gptr) : "memory")

__device__ __forceinline__ float rna(float f) {
    uint32_t r;
    asm("cvt.rna.tf32.f32 %0, %1;" : "=r"(r) : "f"(f));
    return __uint_as_float(r);
}

__device__ __forceinline__ void mma_tf32(float* c, const uint32_t* a,
                                         const uint32_t* b) {
    asm volatile(
        "mma.sync.aligned.m16n8k8.row.col.f32.tf32.tf32.f32 "
        "{%0,%1,%2,%3}, {%4,%5,%6,%7}, {%8,%9}, {%0,%1,%2,%3};"
        : "+f"(c[0]), "+f"(c[1]), "+f"(c[2]), "+f"(c[3])
        : "r"(a[0]), "r"(a[1]), "r"(a[2]), "r"(a[3]), "r"(b[0]), "r"(b[1]));
}

// ---------------------------------------------------------------------------
// Pre-rounding pass: out[i] = tf32_rna(in[i]) (one-time, memory-bound)
// ---------------------------------------------------------------------------
__global__ void round_tf32(const float* __restrict__ in, float* __restrict__ out,
                           int n4) {
    int i = blockIdx.x * blockDim.x + threadIdx.x;
    int stride = gridDim.x * blockDim.x;
    for (; i < n4; i += stride) {
        float4 v = ((const float4*)in)[i];
        v.x = rna(v.x); v.y = rna(v.y); v.z = rna(v.z); v.w = rna(v.w);
        ((float4*)out)[i] = v;
    }
}

// ---------------------------------------------------------------------------
// mma.sync tf32 GEMM (unchanged from R5 WIN): C = A @ W^T (+bias).
// ---------------------------------------------------------------------------
#define GBK 32
#define NKT32 (EE / GBK)
#define SSTR 36
#define TILE_F (128 * SSTR)
#define STAGE_F (2 * TILE_F)
#define GEMM_SMEM (2 * STAGE_F * 4)   // 73728 B

template <int ROUND_OUT>
__global__ __launch_bounds__(256, 2) void gemm_mma(const float* __restrict__ A,
                                                   const float* __restrict__ W,
                                                   const float* __restrict__ bias,
                                                   float* __restrict__ C) {
    extern __shared__ float sm[];
    const int tid = threadIdx.x;
    const int lane = tid & 31;
    const int warp = tid >> 5;
    const int wm = (warp >> 2) * 64;
    const int wn = (warp & 3) * 32;
    const int bm = blockIdx.x * 128;
    const int bn = blockIdx.y * 128;
    const uint32_t sb = smem_u32(sm);

    const int lrow = tid >> 3;
    const int lc4 = (tid & 7) * 4;
    const int lg = lane >> 2;
    const int lk = lane & 3;

    float c[4][4][4];
#pragma unroll
    for (int mt = 0; mt < 4; mt++)
#pragma unroll
        for (int nt = 0; nt < 4; nt++)
#pragma unroll
            for (int i = 0; i < 4; i++) c[mt][nt][i] = 0.0f;

    const float* gA0 = A + (size_t)(bm + lrow) * EE + lc4;
    const float* gW0 = W + (size_t)(bn + lrow) * EE + lc4;
    const uint32_t sOff = (lrow * SSTR + lc4) * 4;

#define LOAD_STAGE(kt, s) do {                                                 \
        const float* _ga = gA0 + (size_t)(kt) * GBK;                           \
        const float* _gw = gW0 + (size_t)(kt) * GBK;                           \
        uint32_t _sa = sb + (uint32_t)((s) * STAGE_F * 4) + sOff;              \
        uint32_t _sw = _sa + TILE_F * 4;                                       \
        _Pragma("unroll")                                                      \
        for (int _u = 0; _u < 4; _u++) {                                       \
            CP_ASYNC16(_sa + _u * 32 * SSTR * 4, _ga + (size_t)_u * 32 * EE);  \
            CP_ASYNC16(_sw + _u * 32 * SSTR * 4, _gw + (size_t)_u * 32 * EE);  \
        }                                                                      \
        asm volatile("cp.async.commit_group;" ::: "memory");                   \
    } while (0)

    LOAD_STAGE(0, 0);

    for (int kt = 0; kt < NKT32; kt++) {
        const int buf = kt & 1;
        if (kt + 1 < NKT32) {
            LOAD_STAGE(kt + 1, buf ^ 1);
            asm volatile("cp.async.wait_group 1;" ::: "memory");
        } else {
            asm volatile("cp.async.wait_group 0;" ::: "memory");
        }
        __syncthreads();

        const float* As = sm + buf * STAGE_F;
        const float* Ws = As + TILE_F;

#pragma unroll
        for (int ks = 0; ks < 4; ks++) {
            const int k0 = ks * 8;
            uint32_t bfr[4][2];
            uint32_t afr[4][4];
#pragma unroll
            for (int nt = 0; nt < 4; nt++) {
                const int r = wn + nt * 8 + lg;
                bfr[nt][0] = __float_as_uint(Ws[r * SSTR + k0 + lk]);
                bfr[nt][1] = __float_as_uint(Ws[r * SSTR + k0 + 4 + lk]);
            }
#pragma unroll
            for (int mt = 0; mt < 4; mt++) {
                const int r = wm + mt * 16 + lg;
                afr[mt][0] = __float_as_uint(As[r * SSTR + k0 + lk]);
                afr[mt][1] = __float_as_uint(As[(r + 8) * SSTR + k0 + lk]);
                afr[mt][2] = __float_as_uint(As[r * SSTR + k0 + 4 + lk]);
                afr[mt][3] = __float_as_uint(As[(r + 8) * SSTR + k0 + 4 + lk]);
            }
#pragma unroll
            for (int mt = 0; mt < 4; mt++)
#pragma unroll
                for (int nt = 0; nt < 4; nt++)
                    mma_tf32(c[mt][nt], afr[mt], bfr[nt]);
        }
        __syncthreads();
    }

#pragma unroll
    for (int mt = 0; mt < 4; mt++) {
        const int r0 = bm + wm + mt * 16 + lg;
#pragma unroll
        for (int nt = 0; nt < 4; nt++) {
            const int col = bn + wn + nt * 8 + lk * 2;
            float bx = 0.0f, by = 0.0f;
            if (bias) { bx = bias[col]; by = bias[col + 1]; }
            float2 v0, v1;
            v0.x = c[mt][nt][0] + bx;
            v0.y = c[mt][nt][1] + by;
            v1.x = c[mt][nt][2] + bx;
            v1.y = c[mt][nt][3] + by;
            if (ROUND_OUT) {
                v0.x = rna(v0.x); v0.y = rna(v0.y);
                v1.x = rna(v1.x); v1.y = rna(v1.y);
            }
            *(float2*)(C + (size_t)r0 * EE + col) = v0;
            *(float2*)(C + (size_t)(r0 + 8) * EE + col) = v1;
        }
    }
}

// ---------------------------------------------------------------------------
// Tensor-core flash attention v2.
// CTA = 256 q-rows x one (b,h); 8 warps x 32 q-rows, full 64-key / 64-d tiles.
// K/V double-buffered via cp.async; mask applied straight from gmem into
// c-fragments; P warp-private (syncwarp only); 1 block barrier per k-tile.
// Strides: AQ/AK/AP=68, AV=72 (conflict-free frag reads; 16B-aligned rows).
// ---------------------------------------------------------------------------
#define AQ 68
#define AK 68
#define AV 72
#define AP 68
#define QF (256 * AQ)                // Q floats
#define STGF (64 * AK + 64 * AV)     // one K+V stage
#define PF (256 * AP)
#define ATTN_SMEM ((QF + 2 * STGF + PF) * 4)   // 210944 B

__global__ __launch_bounds__(256, 1) void attn_tc(const int* __restrict__ mask) {
    extern __shared__ float sm[];
    float* Qs = sm;                       // [256][68]
    float* St = Qs + QF;                  // 2 stages of K[64][68] + V[64][72]
    float* Ps = St + 2 * STGF;            // [256][68], warp-private bands

    const int tid = threadIdx.x;
    const int lane = tid & 31;
    const int warp = tid >> 5;
    const int lg = lane >> 2;
    const int lk = lane & 3;
    const int wq = warp * 32;

    const int bh = blockIdx.y;
    const int b = bh >> 4;
    const int h = bh & 15;
    const int q0 = blockIdx.x * 256;

    const float scale = 0.03125f;          // 2^-5: exact in tf32
    const float mask_addend = -3.125e18f;  // -1e20 * scale

    const uint32_t sb = smem_u32(sm);
    const int ldr = tid >> 4;              // 0..15
    const int ldc = (tid & 15) << 2;       // 0..60

    // Prefetch K/V tile 0 into stage 0
#define PREFETCH_KV(kt, bufsel) do {                                            \
        const uint32_t so = sb + (uint32_t)(QF + (bufsel) * STGF) * 4;          \
        _Pragma("unroll")                                                       \
        for (int _u = 0; _u < 4; _u++) {                                        \
            const int _row = ldr + 16 * _u;                                     \
            const size_t _g = (size_t)(b * LL + (kt) * 64 + _row) * EE          \
                              + h * DD + ldc;                                   \
            CP_ASYNC16(so + (uint32_t)(_row * AK + ldc) * 4, g_k + _g);         \
            CP_ASYNC16(so + (uint32_t)(64 * AK + _row * AV + ldc) * 4,          \
                       g_v + _g);                                               \
        }                                                                       \
        asm volatile("cp.async.commit_group;" ::: "memory");                    \
    } while (0)

    PREFETCH_KV(0, 0);

    // Load Q tile (pre-scaled)
#pragma unroll
    for (int u = 0; u < 16; u++) {
        int idx = tid + 256 * u;
        int row = idx >> 4;
        int c = (idx & 15) << 2;
        float4 q = *(const float4*)(g_q + (size_t)(b * LL + q0 + row) * EE + h * DD + c);
        q.x *= scale; q.y *= scale; q.z *= scale; q.w *= scale;
        *(float4*)(Qs + row * AQ + c) = q;
    }

    float o[2][8][4];
#pragma unroll
    for (int mt = 0; mt < 2; mt++)
#pragma unroll
        for (int dn = 0; dn < 8; dn++)
#pragma unroll
            for (int j = 0; j < 4; j++) o[mt][dn][j] = 0.0f;
    float mrow[2][2], lrow[2][2];
#pragma unroll
    for (int mt = 0; mt < 2; mt++) {
        mrow[mt][0] = -1e30f; mrow[mt][1] = -1e30f;
        lrow[mt][0] = 0.0f;   lrow[mt][1] = 0.0f;
    }

    const size_t mask_b = (size_t)b * LL * LL;

    for (int kt = 0; kt < LL / 64; kt++) {
        const int k0g = kt * 64;
        const int buf = kt & 1;

        asm volatile("cp.async.wait_group 0;" ::: "memory");
        __syncthreads();   // tile kt visible to all; all warps done with kt-1

        if (kt + 1 < LL / 64) PREFETCH_KV(kt + 1, buf ^ 1);

        const float* Ks = St + buf * STGF;
        const float* Vs = Ks + 64 * AK;

        // ---- S = Q @ K^T ----
        float s[2][8][4];
#pragma unroll
        for (int mt = 0; mt < 2; mt++)
#pragma unroll
            for (int nt = 0; nt < 8; nt++)
#pragma unroll
                for (int j = 0; j < 4; j++) s[mt][nt][j] = 0.0f;

#pragma unroll
        for (int ks = 0; ks < 8; ks++) {
            const int k0 = ks * 8;
            uint32_t a[2][4];
#pragma unroll
            for (int mt = 0; mt < 2; mt++) {
                const int r = wq + mt * 16 + lg;
                a[mt][0] = __float_as_uint(Qs[r * AQ + k0 + lk]);
                a[mt][1] = __float_as_uint(Qs[(r + 8) * AQ + k0 + lk]);
                a[mt][2] = __float_as_uint(Qs[r * AQ + k0 + 4 + lk]);
                a[mt][3] = __float_as_uint(Qs[(r + 8) * AQ + k0 + 4 + lk]);
            }
#pragma unroll
            for (int nt = 0; nt < 8; nt++) {
                uint32_t bf[2];
                bf[0] = __float_as_uint(Ks[(nt * 8 + lg) * AK + k0 + lk]);
                bf[1] = __float_as_uint(Ks[(nt * 8 + lg) * AK + k0 + 4 + lk]);
                mma_tf32(s[0][nt], a[0], bf);
                mma_tf32(s[1][nt], a[1], bf);
            }
        }

        // ---- mask (masked_fill semantics), straight from gmem ----
#pragma unroll
        for (int mt = 0; mt < 2; mt++) {
            const int qrow = q0 + wq + mt * 16 + lg;
            const size_t mrow0 = mask_b + (size_t)qrow * LL + k0g + 2 * lk;
            const size_t mrow1 = mask_b + (size_t)(qrow + 8) * LL + k0g + 2 * lk;
#pragma unroll
            for (int nt = 0; nt < 8; nt++) {
                int2 ma = *(const int2*)(mask + mrow0 + nt * 8);
                int2 mb = *(const int2*)(mask + mrow1 + nt * 8);
                if (ma.x == 0) s[mt][nt][0] = mask_addend;
                if (ma.y == 0) s[mt][nt][1] = mask_addend;
                if (mb.x == 0) s[mt][nt][2] = mask_addend;
                if (mb.y == 0) s[mt][nt][3] = mask_addend;
            }
        }

        // ---- online softmax + P store (warp-private band) ----
#pragma unroll
        for (int mt = 0; mt < 2; mt++) {
            float mx0 = s[mt][0][0], mx1 = s[mt][0][2];
#pragma unroll
            for (int nt = 0; nt < 8; nt++) {
                mx0 = fmaxf(mx0, fmaxf(s[mt][nt][0], s[mt][nt][1]));
                mx1 = fmaxf(mx1, fmaxf(s[mt][nt][2], s[mt][nt][3]));
            }
            mx0 = fmaxf(mx0, __shfl_xor_sync(0xffffffffu, mx0, 1));
            mx0 = fmaxf(mx0, __shfl_xor_sync(0xffffffffu, mx0, 2));
            mx1 = fmaxf(mx1, __shfl_xor_sync(0xffffffffu, mx1, 1));
            mx1 = fmaxf(mx1, __shfl_xor_sync(0xffffffffu, mx1, 2));
            float mn0 = fmaxf(mrow[mt][0], mx0), mn1 = fmaxf(mrow[mt][1], mx1);
            float al0 = __expf(mrow[mt][0] - mn0), al1 = __expf(mrow[mt][1] - mn1);
            mrow[mt][0] = mn0; mrow[mt][1] = mn1;
            float sum0 = 0.0f, sum1 = 0.0f;
#pragma unroll
            for (int nt = 0; nt < 8; nt++) {
                s[mt][nt][0] = __expf(s[mt][nt][0] - mn0);
                s[mt][nt][1] = __expf(s[mt][nt][1] - mn0);
                s[mt][nt][2] = __expf(s[mt][nt][2] - mn1);
                s[mt][nt][3] = __expf(s[mt][nt][3] - mn1);
                sum0 += s[mt][nt][0] + s[mt][nt][1];
                sum1 += s[mt][nt][2] + s[mt][nt][3];
            }
            sum0 += __shfl_xor_sync(0xffffffffu, sum0, 1);
            sum0 += __shfl_xor_sync(0xffffffffu, sum0, 2);
            sum1 += __shfl_xor_sync(0xffffffffu, sum1, 1);
            sum1 += __shfl_xor_sync(0xffffffffu, sum1, 2);
            lrow[mt][0] = lrow[mt][0] * al0 + sum0;
            lrow[mt][1] = lrow[mt][1] * al1 + sum1;
#pragma unroll
            for (int dn = 0; dn < 8; dn++) {
                o[mt][dn][0] *= al0; o[mt][dn][1] *= al0;
                o[mt][dn][2] *= al1; o[mt][dn][3] *= al1;
            }
            const int r = wq + mt * 16 + lg;
#pragma unroll
            for (int nt = 0; nt < 8; nt++) {
                float2 t0, t1;
                t0.x = rna(s[mt][nt][0]); t0.y = rna(s[mt][nt][1]);
                t1.x = rna(s[mt][nt][2]); t1.y = rna(s[mt][nt][3]);
                *(float2*)(Ps + r * AP + nt * 8 + 2 * lk) = t0;
                *(float2*)(Ps + (r + 8) * AP + nt * 8 + 2 * lk) = t1;
            }
        }
        __syncwarp();

        // ---- O += P @ V ----
#pragma unroll
        for (int ks = 0; ks < 8; ks++) {
            const int k0 = ks * 8;
            uint32_t a[2][4];
#pragma unroll
            for (int mt = 0; mt < 2; mt++) {
                const int r = wq + mt * 16 + lg;
                a[mt][0] = __float_as_uint(Ps[r * AP + k0 + lk]);
                a[mt][1] = __float_as_uint(Ps[(r + 8) * AP + k0 + lk]);
                a[mt][2] = __float_as_uint(Ps[r * AP + k0 + 4 + lk]);
                a[mt][3] = __float_as_uint(Ps[(r + 8) * AP + k0 + 4 + lk]);
            }
#pragma unroll
            for (int dn = 0; dn < 8; dn++) {
                uint32_t bf[2];
                bf[0] = __float_as_uint(Vs[(k0 + lk) * AV + dn * 8 + lg]);
                bf[1] = __float_as_uint(Vs[(k0 + 4 + lk) * AV + dn * 8 + lg]);
                mma_tf32(o[0][dn], a[0], bf);
                mma_tf32(o[1][dn], a[1], bf);
            }
        }
    }

    // Epilogue: normalize, round to tf32 (final GEMM input), store ctx
#pragma unroll
    for (int mt = 0; mt < 2; mt++) {
        float inv0 = 1.0f / lrow[mt][0], inv1 = 1.0f / lrow[mt][1];
        const size_t r0 = (size_t)(b * LL + q0 + wq + mt * 16 + lg) * EE + h * DD;
        const size_t r1 = r0 + 8 * EE;
#pragma unroll
        for (int dn = 0; dn < 8; dn++) {
            const int col = dn * 8 + 2 * lk;
            float2 v0, v1;
            v0.x = rna(o[mt][dn][0] * inv0); v0.y = rna(o[mt][dn][1] * inv0);
            v1.x = rna(o[mt][dn][2] * inv1); v1.y = rna(o[mt][dn][3] * inv1);
            *(float2*)(g_ctx + r0 + col) = v0;
            *(float2*)(g_ctx + r1 + col) = v1;
        }
    }
}

// ---------------------------------------------------------------------------
// Launch
// ---------------------------------------------------------------------------
extern "C" void kernel_launch(void* const* d_in, const int* in_sizes, int n_in,
                              void* d_out, int out_size) {
    const float* queries = (const float*)d_in[0];
    const float* keys    = (const float*)d_in[1];
    const float* values  = (const float*)d_in[2];
    const int*   mask    = (const int*)d_in[3];
    const float* Wq      = (const float*)d_in[4];
    const float* Wk      = (const float*)d_in[5];
    const float* Wv      = (const float*)d_in[6];
    const float* Wo      = (const float*)d_in[7];
    const float* bo      = (const float*)d_in[8];
    float* out = (float*)d_out;

    float *q, *k, *v, *ctx, *rq, *rk, *rv, *rw;
    cudaGetSymbolAddress((void**)&q,   g_q);
    cudaGetSymbolAddress((void**)&k,   g_k);
    cudaGetSymbolAddress((void**)&v,   g_v);
    cudaGetSymbolAddress((void**)&ctx, g_ctx);
    cudaGetSymbolAddress((void**)&rq,  g_rq);
    cudaGetSymbolAddress((void**)&rk,  g_rk);
    cudaGetSymbolAddress((void**)&rv,  g_rv);
    cudaGetSymbolAddress((void**)&rw,  g_rw);

    cudaFuncSetAttribute(gemm_mma<0>, cudaFuncAttributeMaxDynamicSharedMemorySize,
                         GEMM_SMEM);
    cudaFuncSetAttribute(gemm_mma<1>, cudaFuncAttributeMaxDynamicSharedMemorySize,
                         GEMM_SMEM);
    cudaFuncSetAttribute(attn_tc, cudaFuncAttributeMaxDynamicSharedMemorySize,
                         ATTN_SMEM);

    // Pre-round inputs + weights to tf32 (RNA) once
    const int n4in = ML * EE / 4;
    const int n4w  = EE * EE / 4;
    round_tf32<<<512, 256>>>(queries, rq, n4in);
    round_tf32<<<512, 256>>>(keys,    rk, n4in);
    round_tf32<<<512, 256>>>(values,  rv, n4in);
    round_tf32<<<256, 256>>>(Wq, rw + 0 * EE * EE, n4w);
    round_tf32<<<256, 256>>>(Wk, rw + 1 * EE * EE, n4w);
    round_tf32<<<256, 256>>>(Wv, rw + 2 * EE * EE, n4w);
    round_tf32<<<256, 256>>>(Wo, rw + 3 * EE * EE, n4w);

    dim3 gg(ML / 128, EE / 128);   // 64 x 8
    gemm_mma<1><<<gg, 256, GEMM_SMEM>>>(rq, rw + 0 * EE * EE, nullptr, q);
    gemm_mma<1><<<gg, 256, GEMM_SMEM>>>(rk, rw + 1 * EE * EE, nullptr, k);
    gemm_mma<1><<<gg, 256, GEMM_SMEM>>>(rv, rw + 2 * EE * EE, nullptr, v);

    dim3 ga(LL / 256, BB * HH);    // 8 x 64
    attn_tc<<<ga, 256, ATTN_SMEM>>>(mask);

    gemm_mma<0><<<gg, 256, GEMM_SMEM>>>(ctx, rw + 3 * EE * EE, bo, out);
}